// round 14
// baseline (speedup 1.0000x reference)
#include <cuda_runtime.h>
#include <cuda_fp16.h>
#include <cstdint>
#include <cstddef>

// ============================ problem dims ============================
#define MDIM 8192
#define NDIM 4096
#define KDIM 4096

// ============================ scratch (no allocs allowed) =============
__device__ __half g_Xh[(size_t)MDIM * KDIM];   // 67 MB fp16 activations
__device__ __half g_Wh[(size_t)NDIM * KDIM];   // 34 MB fp16 ternary weights
__device__ float  g_partf[2048];
__device__ float  g_gamma;
__device__ int    g_cnt = 0;                   // last-block pattern (self-resetting)

// ============================ PTX helpers =============================
__device__ __forceinline__ uint32_t s2u(const void* p) {
    uint32_t a;
    asm("{ .reg .u64 t; cvta.to.shared.u64 t, %1; cvt.u32.u64 %0, t; }"
        : "=r"(a) : "l"(p));
    return a;
}

#define CP16(dst, src) \
    asm volatile("cp.async.cg.shared.global [%0], [%1], 16;" :: "r"(dst), "l"(src))
#define CP_COMMIT() asm volatile("cp.async.commit_group;" ::: "memory")
#define CP_WAIT(n)  asm volatile("cp.async.wait_group %0;" :: "n"(n) : "memory")

#define LDSM_X4(r0, r1, r2, r3, addr) \
    asm volatile("ldmatrix.sync.aligned.m8n8.x4.shared.b16 {%0,%1,%2,%3}, [%4];" \
                 : "=r"(r0), "=r"(r1), "=r"(r2), "=r"(r3) : "r"(addr))

#define MMA16816(c, a, b) \
    asm volatile("mma.sync.aligned.m16n8k16.row.col.f32.f16.f16.f32 " \
                 "{%0,%1,%2,%3}, {%4,%5,%6,%7}, {%8,%9}, {%0,%1,%2,%3};" \
                 : "+f"((c)[0]), "+f"((c)[1]), "+f"((c)[2]), "+f"((c)[3]) \
                 : "r"((a)[0]), "r"((a)[1]), "r"((a)[2]), "r"((a)[3]), \
                   "r"((b)[0]), "r"((b)[1]))

// ============================ prepass kernels =========================
// blocks [0,2048): fp32 |W| partial sums; the LAST absum block to finish also
// computes gamma (bit-identical double reduction) — no separate launch.
// blocks [2048,18432): convert X->fp16.
__global__ void absumconv_kernel(const float* __restrict__ w,
                                 const float* __restrict__ x) {
    if (blockIdx.x < 2048) {
        __shared__ float sh[256];
        __shared__ bool amLast;
        int tid = threadIdx.x;
        const float4* src = (const float4*)(w + (size_t)blockIdx.x * 8192) + tid;
        float s0 = 0.f, s1 = 0.f, s2 = 0.f, s3 = 0.f;   // 4-lane ILP
        #pragma unroll
        for (int i = 0; i < 8; i++) {
            float4 v = src[i * 256];
            s0 += fabsf(v.x); s1 += fabsf(v.y);
            s2 += fabsf(v.z); s3 += fabsf(v.w);
        }
        sh[tid] = (s0 + s1) + (s2 + s3);
        __syncthreads();
        for (int off = 128; off; off >>= 1) {
            if (tid < off) sh[tid] += sh[tid + off];
            __syncthreads();
        }
        if (tid == 0) g_partf[blockIdx.x] = sh[0];
        // last-block gamma (threadFenceReduction pattern)
        __threadfence();
        if (tid == 0) amLast = (atomicAdd(&g_cnt, 1) == 2047);
        __syncthreads();
        if (amLast) {
            __shared__ double dh[256];
            double s = 0.0;
            #pragma unroll
            for (int i = 0; i < 8; i++) s += (double)g_partf[tid * 8 + i];
            dh[tid] = s; __syncthreads();
            for (int off = 128; off; off >>= 1) {
                if (tid < off) dh[tid] += dh[tid + off];
                __syncthreads();
            }
            if (tid == 0) {
                float gm = (float)(dh[0] / 16777216.0);
                g_gamma = fmaxf(gm, 1e-8f);
                __threadfence();
                g_cnt = 0;                 // reset for graph replay
            }
        }
    } else {
        size_t base = (((size_t)blockIdx.x - 2048) * 256 + threadIdx.x) * 8;
        float4 a = *(const float4*)(x + base);
        float4 b = *(const float4*)(x + base + 4);
        __half h[8] = {__float2half_rn(a.x), __float2half_rn(a.y),
                       __float2half_rn(a.z), __float2half_rn(a.w),
                       __float2half_rn(b.x), __float2half_rn(b.y),
                       __float2half_rn(b.z), __float2half_rn(b.w)};
        *(uint4*)(&g_Xh[base]) = *(const uint4*)h;
    }
}

// ternary-quantize W into fp16 ({-1,0,1} exact in fp16)
__global__ void quantw_kernel(const float* __restrict__ w) {
    float g = g_gamma;
    size_t base = ((size_t)blockIdx.x * 256 + threadIdx.x) * 8;
    float4 a = *(const float4*)(w + base);
    float4 b = *(const float4*)(w + base + 4);
    float v[8] = {a.x, a.y, a.z, a.w, b.x, b.y, b.z, b.w};
    __half h[8];
    #pragma unroll
    for (int i = 0; i < 8; i++) {
        float q = rintf(__fdiv_rn(v[i], g));   // round-half-even, IEEE div
        q = fminf(fmaxf(q, -1.0f), 1.0f);
        h[i] = __float2half_rn(q);
    }
    *(uint4*)(&g_Wh[base]) = *(const uint4*)h;
}

// ============================ GEMM kernel =============================
// PERSISTENT: grid=296 (=148 SMs x 2 CTAs). Each CTA walks tiles
// t = cta, cta+296, ... with a load cursor that runs ahead of compute and
// crosses tile boundaries, so the 3-stage cp.async pipeline NEVER drains.
// CTA tile 128x128, 4 warps (2x2), warp tile 64x64, 96 KB SMEM, 2 CTAs/SM.
#define BM 128
#define BN 128
#define KSTEP 64
#define NK (KDIM / KSTEP)                 // 64
#define STAGES 3
#define A_BYTES (BM * 128)                // 16 KB
#define B_BYTES (BN * 128)                // 16 KB
#define STG_BYTES (A_BYTES + B_BYTES)     // 32 KB
#define SMEM_TOTAL (STAGES * STG_BYTES)   // 96 KB
#define NTILES 2048
#define NCTAS 296

__global__ void __launch_bounds__(128, 2)
gemm_kernel(float* __restrict__ out, const float* __restrict__ bias) {
    extern __shared__ char smem[];
    uint32_t sb = s2u(smem);
    int tid = threadIdx.x, wid = tid >> 5, lid = tid & 31;
    int cta = blockIdx.x;
    int wm = (wid >> 1) * 64;
    int wn = (wid & 1) * 64;

    int a_row = wm + (lid & 15);
    int a_ks  = lid >> 4;
    int b_row = wn + ((lid >> 4) << 3) + (lid & 7);
    int b_ks  = (lid >> 3) & 1;

    // per-thread fixed copy geometry
    int c_row = tid >> 3;                 // 0..15
    int c_ch  = tid & 7;                  // 0..7
    uint32_t dstoffA = c_row * 128 + ((c_ch ^ (c_row & 7)) << 4);

    // ---- load cursor (runs ahead of compute, crosses tiles) ----
    int l_t = cta;                        // tile being loaded
    int l_kt = 0;                         // stage within l_t
    const __half *lA0, *lB0;
    auto set_srcs = [&](int t) {
        int lm = (t & 63) * BM, ln = (t >> 6) * BN;
        lA0 = &g_Xh[(size_t)(lm + c_row) * KDIM + c_ch * 8];
        lB0 = &g_Wh[(size_t)(ln + c_row) * KDIM + c_ch * 8];
    };
    set_srcs(l_t);

    // issue 2 A + 2 B chunks (quarter stage) of cursor stage into buffer buf
    auto load_quarter = [&](int buf, int p) {
        int k0 = l_kt * KSTEP;
        uint32_t sA = sb + buf * STG_BYTES;
        uint32_t sB = sA + A_BYTES;
        #pragma unroll
        for (int i = p * 2; i < p * 2 + 2; i++) {
            CP16(sA + dstoffA + i * 2048, lA0 + (size_t)i * 16 * KDIM + k0);
            CP16(sB + dstoffA + i * 2048, lB0 + (size_t)i * 16 * KDIM + k0);
        }
    };
    auto cursor_advance = [&]() {
        if (++l_kt == NK) { l_kt = 0; l_t += NCTAS; if (l_t < NTILES) set_srcs(l_t); }
    };

    // prologue: fill stages 0,1 of first tile
    #pragma unroll
    for (int s = 0; s < STAGES - 1; s++) {
        #pragma unroll
        for (int p = 0; p < 4; p++) load_quarter(s, p);
        CP_COMMIT();
        cursor_advance();
    }

    uint32_t af[4][4], bf[4][4];
    int cbuf = 0, pbuf = STAGES - 1;      // compute buf / prefetch buf

    #pragma unroll 1
    for (int t = cta; t < NTILES; t += NCTAS) {
        int m0 = (t & 63) * BM;
        int n0 = (t >> 6) * BN;

        float acc[4][8][4];
        #pragma unroll
        for (int i = 0; i < 4; i++)
            #pragma unroll
            for (int j = 0; j < 8; j++)
                #pragma unroll
                for (int r = 0; r < 4; r++) acc[i][j][r] = 0.0f;

        #pragma unroll 3
        for (int kt = 0; kt < NK; kt++) {
            CP_WAIT(STAGES - 2);          // oldest group landed
            __syncthreads();

            uint32_t sA = sb + cbuf * STG_BYTES;
            uint32_t sB = sA + A_BYTES;
            bool do_load = (l_t < NTILES);

            #pragma unroll
            for (int kk = 0; kk < 4; kk++) {
                #pragma unroll
                for (int mi = 0; mi < 4; mi++) {
                    int m = a_row + mi * 16;
                    int kch = kk * 2 + a_ks;
                    uint32_t ad = sA + m * 128 + ((kch ^ (m & 7)) << 4);
                    LDSM_X4(af[mi][0], af[mi][1], af[mi][2], af[mi][3], ad);
                }
                #pragma unroll
                for (int ni = 0; ni < 4; ni++) {
                    int n = b_row + ni * 16;
                    int kch = kk * 2 + b_ks;
                    uint32_t bd = sB + n * 128 + ((kch ^ (n & 7)) << 4);
                    LDSM_X4(bf[ni][0], bf[ni][1], bf[ni][2], bf[ni][3], bd);
                }
                if (do_load) load_quarter(pbuf, kk);
                #pragma unroll
                for (int mi = 0; mi < 4; mi++)
                    #pragma unroll
                    for (int nj = 0; nj < 8; nj++) {
                        uint32_t bb[2] = {bf[nj >> 1][(nj & 1) * 2],
                                          bf[nj >> 1][(nj & 1) * 2 + 1]};
                        MMA16816(acc[mi][nj], af[mi], bb);
                    }
            }
            CP_COMMIT();                  // uniform group accounting (may be empty)
            if (do_load) cursor_advance();
            cbuf = (cbuf == STAGES - 1) ? 0 : cbuf + 1;
            pbuf = (pbuf == STAGES - 1) ? 0 : pbuf + 1;
        }

        // ---- epilogue for tile t (next tile's loads already in flight) ----
        #pragma unroll
        for (int nj = 0; nj < 8; nj++) {
            int n = n0 + wn + nj * 8 + (lid & 3) * 2;
            float2 bv = *(const float2*)(bias + n);
            #pragma unroll
            for (int mi = 0; mi < 4; mi++) {
                int m = m0 + wm + mi * 16 + (lid >> 2);
                float2 v0 = {acc[mi][nj][0] + bv.x, acc[mi][nj][1] + bv.y};
                float2 v1 = {acc[mi][nj][2] + bv.x, acc[mi][nj][3] + bv.y};
                *(float2*)(out + (size_t)m * NDIM + n) = v0;
                *(float2*)(out + (size_t)(m + 8) * NDIM + n) = v1;
            }
        }
    }
}

// ============================ launch ==================================
extern "C" void kernel_launch(void* const* d_in, const int* in_sizes, int n_in,
                              void* d_out, int out_size) {
    const float* x    = (const float*)d_in[0];
    const float* w    = (const float*)d_in[1];
    const float* bias = (const float*)d_in[2];
    float* out = (float*)d_out;

    absumconv_kernel<<<18432, 256>>>(w, x);   // fp32 absum + last-block gamma ∥ convx
    quantw_kernel<<<8192, 256>>>(w);

    cudaFuncSetAttribute(gemm_kernel, cudaFuncAttributeMaxDynamicSharedMemorySize,
                         SMEM_TOTAL);
    gemm_kernel<<<NCTAS, 128, SMEM_TOTAL>>>(out, bias);
}

// round 15
// speedup vs baseline: 1.0816x; 1.0816x over previous
#include <cuda_runtime.h>
#include <cuda_fp16.h>
#include <cstdint>
#include <cstddef>

// ============================ problem dims ============================
#define MDIM 8192
#define NDIM 4096
#define KDIM 4096

// ============================ scratch (no allocs allowed) =============
__device__ __half g_Xh[(size_t)MDIM * KDIM];   // 67 MB fp16 activations
__device__ __half g_Wh[(size_t)NDIM * KDIM];   // 34 MB fp16 ternary weights
__device__ float  g_partf[2048];
__device__ float  g_gamma;
__device__ int    g_cnt = 0;                   // last-block pattern (self-resetting)

// ============================ PTX helpers =============================
__device__ __forceinline__ uint32_t s2u(const void* p) {
    uint32_t a;
    asm("{ .reg .u64 t; cvta.to.shared.u64 t, %1; cvt.u32.u64 %0, t; }"
        : "=r"(a) : "l"(p));
    return a;
}

#define CP16(dst, src) \
    asm volatile("cp.async.cg.shared.global [%0], [%1], 16;" :: "r"(dst), "l"(src))
#define CP_COMMIT() asm volatile("cp.async.commit_group;" ::: "memory")
#define CP_WAIT(n)  asm volatile("cp.async.wait_group %0;" :: "n"(n) : "memory")

#define LDSM_X4(r0, r1, r2, r3, addr) \
    asm volatile("ldmatrix.sync.aligned.m8n8.x4.shared.b16 {%0,%1,%2,%3}, [%4];" \
                 : "=r"(r0), "=r"(r1), "=r"(r2), "=r"(r3) : "r"(addr))

#define MMA16816(c, a, b) \
    asm volatile("mma.sync.aligned.m16n8k16.row.col.f32.f16.f16.f32 " \
                 "{%0,%1,%2,%3}, {%4,%5,%6,%7}, {%8,%9}, {%0,%1,%2,%3};" \
                 : "+f"((c)[0]), "+f"((c)[1]), "+f"((c)[2]), "+f"((c)[3]) \
                 : "r"((a)[0]), "r"((a)[1]), "r"((a)[2]), "r"((a)[3]), \
                   "r"((b)[0]), "r"((b)[1]))

// ============================ prepass kernels =========================
// blocks [0,2048): fp32 |W| partial sums; the LAST absum block to finish also
// computes gamma (bit-identical double reduction) — no separate launch.
// blocks [2048,18432): convert X->fp16.
__global__ void absumconv_kernel(const float* __restrict__ w,
                                 const float* __restrict__ x) {
    if (blockIdx.x < 2048) {
        __shared__ float sh[256];
        __shared__ bool amLast;
        int tid = threadIdx.x;
        const float4* src = (const float4*)(w + (size_t)blockIdx.x * 8192) + tid;
        float s0 = 0.f, s1 = 0.f, s2 = 0.f, s3 = 0.f;   // 4-lane ILP
        #pragma unroll
        for (int i = 0; i < 8; i++) {
            float4 v = src[i * 256];
            s0 += fabsf(v.x); s1 += fabsf(v.y);
            s2 += fabsf(v.z); s3 += fabsf(v.w);
        }
        sh[tid] = (s0 + s1) + (s2 + s3);
        __syncthreads();
        for (int off = 128; off; off >>= 1) {
            if (tid < off) sh[tid] += sh[tid + off];
            __syncthreads();
        }
        if (tid == 0) g_partf[blockIdx.x] = sh[0];
        // last-block gamma (threadFenceReduction pattern)
        __threadfence();
        if (tid == 0) amLast = (atomicAdd(&g_cnt, 1) == 2047);
        __syncthreads();
        if (amLast) {
            __shared__ double dh[256];
            double s = 0.0;
            #pragma unroll
            for (int i = 0; i < 8; i++) s += (double)g_partf[tid * 8 + i];
            dh[tid] = s; __syncthreads();
            for (int off = 128; off; off >>= 1) {
                if (tid < off) dh[tid] += dh[tid + off];
                __syncthreads();
            }
            if (tid == 0) {
                float gm = (float)(dh[0] / 16777216.0);
                g_gamma = fmaxf(gm, 1e-8f);
                __threadfence();
                g_cnt = 0;                 // reset for graph replay
            }
        }
    } else {
        size_t base = (((size_t)blockIdx.x - 2048) * 256 + threadIdx.x) * 8;
        float4 a = *(const float4*)(x + base);
        float4 b = *(const float4*)(x + base + 4);
        __half h[8] = {__float2half_rn(a.x), __float2half_rn(a.y),
                       __float2half_rn(a.z), __float2half_rn(a.w),
                       __float2half_rn(b.x), __float2half_rn(b.y),
                       __float2half_rn(b.z), __float2half_rn(b.w)};
        *(uint4*)(&g_Xh[base]) = *(const uint4*)h;
    }
}

// ternary-quantize W into fp16 ({-1,0,1} exact in fp16)
__global__ void quantw_kernel(const float* __restrict__ w) {
    float g = g_gamma;
    size_t base = ((size_t)blockIdx.x * 256 + threadIdx.x) * 8;
    float4 a = *(const float4*)(w + base);
    float4 b = *(const float4*)(w + base + 4);
    float v[8] = {a.x, a.y, a.z, a.w, b.x, b.y, b.z, b.w};
    __half h[8];
    #pragma unroll
    for (int i = 0; i < 8; i++) {
        float q = rintf(__fdiv_rn(v[i], g));   // round-half-even, IEEE div
        q = fminf(fmaxf(q, -1.0f), 1.0f);
        h[i] = __float2half_rn(q);
    }
    *(uint4*)(&g_Wh[base]) = *(const uint4*)h;
}

// ============================ GEMM kernel =============================
// R13 GEMM, byte-identical (best measured: 529.9us, tensor 85.7%).
// CTA 128(M) x 128(N), 128 thr = 4 warps (2x2), warp tile 64x64.
// 3-stage cp.async pipeline (96 KB) -> 2 CTAs/SM.
// NOTE on wait depth: each iteration commits its stage-load group at the END
// of the iteration, so at the loop head exactly 2 groups are pending and
// CP_WAIT(STAGES-2)=1 waits for precisely the oldest (buffer kt) — correct
// and optimal. WAIT(2) here is a no-op and reads unloaded data (R10 failure).
// Persistent-CTA variant measured +46us (R14) — do not revisit.
#define BM 128
#define BN 128
#define KSTEP 64
#define NK (KDIM / KSTEP)                 // 64
#define STAGES 3
#define A_BYTES (BM * 128)                // 16 KB
#define B_BYTES (BN * 128)                // 16 KB
#define STG_BYTES (A_BYTES + B_BYTES)     // 32 KB
#define SMEM_TOTAL (STAGES * STG_BYTES)   // 96 KB

__global__ void __launch_bounds__(128, 2)
gemm_kernel(float* __restrict__ out, const float* __restrict__ bias) {
    extern __shared__ char smem[];
    uint32_t sb = s2u(smem);
    int tid = threadIdx.x, wid = tid >> 5, lid = tid & 31;
    int m0 = blockIdx.x * BM;
    int n0 = blockIdx.y * BN;
    int wm = (wid >> 1) * 64;
    int wn = (wid & 1) * 64;

    int a_row = wm + (lid & 15);
    int a_ks  = lid >> 4;
    int b_row = wn + ((lid >> 4) << 3) + (lid & 7);
    int b_ks  = (lid >> 3) & 1;

    // per-thread fixed copy geometry: 8 A-chunks + 8 B-chunks per stage
    int c_row = tid >> 3;                 // 0..15
    int c_ch  = tid & 7;                  // 0..7
    uint32_t dstoffA = c_row * 128 + ((c_ch ^ (c_row & 7)) << 4);  // +i*16 rows
    const __half* srcA0 = &g_Xh[(size_t)(m0 + c_row) * KDIM + c_ch * 8];
    const __half* srcB0 = &g_Wh[(size_t)(n0 + c_row) * KDIM + c_ch * 8];

    float acc[4][8][4];
    #pragma unroll
    for (int i = 0; i < 4; i++)
        #pragma unroll
        for (int j = 0; j < 8; j++)
            #pragma unroll
            for (int r = 0; r < 4; r++) acc[i][j][r] = 0.0f;

    // issue 2 A-chunks + 2 B-chunks (quarter of a stage) for part p in 0..3
    auto load_quarter = [&](int buf, int kt, int p) {
        int k0 = kt * KSTEP;
        uint32_t sA = sb + buf * STG_BYTES;
        uint32_t sB = sA + A_BYTES;
        #pragma unroll
        for (int i = p * 2; i < p * 2 + 2; i++) {
            CP16(sA + dstoffA + i * 2048, srcA0 + (size_t)i * 16 * KDIM + k0);
            CP16(sB + dstoffA + i * 2048, srcB0 + (size_t)i * 16 * KDIM + k0);
        }
    };

    auto load_stage = [&](int buf, int kt) {
        #pragma unroll
        for (int p = 0; p < 4; p++) load_quarter(buf, kt, p);
    };

    #pragma unroll
    for (int s = 0; s < STAGES - 1; s++) { load_stage(s, s); CP_COMMIT(); }

    uint32_t af[4][4], bf[4][4];

    #pragma unroll 3
    for (int kt = 0; kt < NK; kt++) {
        CP_WAIT(STAGES - 2);              // oldest group (buffer kt) landed
        __syncthreads();

        int buf = kt % STAGES;
        int nk = kt + STAGES - 1;
        int pbuf = nk % STAGES;
        uint32_t sA = sb + buf * STG_BYTES;
        uint32_t sB = sA + A_BYTES;
        bool do_load = (nk < NK);

        #pragma unroll
        for (int kk = 0; kk < 4; kk++) {
            #pragma unroll
            for (int mi = 0; mi < 4; mi++) {
                int m = a_row + mi * 16;
                int kch = kk * 2 + a_ks;
                uint32_t ad = sA + m * 128 + ((kch ^ (m & 7)) << 4);
                LDSM_X4(af[mi][0], af[mi][1], af[mi][2], af[mi][3], ad);
            }
            #pragma unroll
            for (int ni = 0; ni < 4; ni++) {
                int n = b_row + ni * 16;
                int kch = kk * 2 + b_ks;
                uint32_t bd = sB + n * 128 + ((kch ^ (n & 7)) << 4);
                LDSM_X4(bf[ni][0], bf[ni][1], bf[ni][2], bf[ni][3], bd);
            }
            // quarter of next stage's copies rides under this kk's MMAs
            if (do_load) load_quarter(pbuf, nk, kk);
            #pragma unroll
            for (int mi = 0; mi < 4; mi++)
                #pragma unroll
                for (int nj = 0; nj < 8; nj++) {
                    uint32_t bb[2] = {bf[nj >> 1][(nj & 1) * 2],
                                      bf[nj >> 1][(nj & 1) * 2 + 1]};
                    MMA16816(acc[mi][nj], af[mi], bb);
                }
        }
        CP_COMMIT();
    }

    // ---- epilogue: direct reg -> global with bias ----
    #pragma unroll
    for (int nj = 0; nj < 8; nj++) {
        int n = n0 + wn + nj * 8 + (lid & 3) * 2;
        float2 bv = *(const float2*)(bias + n);
        #pragma unroll
        for (int mi = 0; mi < 4; mi++) {
            int m = m0 + wm + mi * 16 + (lid >> 2);
            float2 v0 = {acc[mi][nj][0] + bv.x, acc[mi][nj][1] + bv.y};
            float2 v1 = {acc[mi][nj][2] + bv.x, acc[mi][nj][3] + bv.y};
            *(float2*)(out + (size_t)m * NDIM + n) = v0;
            *(float2*)(out + (size_t)(m + 8) * NDIM + n) = v1;
        }
    }
}

// ============================ launch ==================================
extern "C" void kernel_launch(void* const* d_in, const int* in_sizes, int n_in,
                              void* d_out, int out_size) {
    const float* x    = (const float*)d_in[0];
    const float* w    = (const float*)d_in[1];
    const float* bias = (const float*)d_in[2];
    float* out = (float*)d_out;

    absumconv_kernel<<<18432, 256>>>(w, x);   // fp32 absum + last-block gamma ∥ convx
    quantw_kernel<<<8192, 256>>>(w);

    cudaFuncSetAttribute(gemm_kernel, cudaFuncAttributeMaxDynamicSharedMemorySize,
                         SMEM_TOTAL);
    gemm_kernel<<<dim3(MDIM / BM, NDIM / BN), 128, SMEM_TOTAL>>>(out, bias);
}